// round 1
// baseline (speedup 1.0000x reference)
#include <cuda_runtime.h>
#include <cuda_bf16.h>
#include <float.h>

#define NUM_EMB   8192
#define DIM       4
#define NTOK      32768          // B*L = 8*4096
#define NELEM     131072.0f     // B*L*DIM
#define THREADS   256
#define GRID      128           // GRID*THREADS == NTOK

// scratch for per-block partial sums (no device allocation allowed)
__device__ float g_blocksums[GRID];

__global__ __launch_bounds__(THREADS, 1)
void vq_main_kernel(const float4* __restrict__ x,
                    const float4* __restrict__ emb)
{
    extern __shared__ float4 semb[];   // 8192 * 16B = 128 KB

    // cooperative load of the whole codebook into shared memory
    #pragma unroll 4
    for (int i = threadIdx.x; i < NUM_EMB; i += THREADS) {
        semb[i] = emb[i];
    }
    __syncthreads();

    const int tok = blockIdx.x * THREADS + threadIdx.x;
    const float4 xv = x[tok];

    float best = -FLT_MAX;
    int   bidx = 0;

    // all lanes process the same embedding index each step -> LDS broadcast
    #pragma unroll 8
    for (int i = 0; i < NUM_EMB; ++i) {
        const float4 e = semb[i];
        float d = xv.x * e.x;
        d = fmaf(xv.y, e.y, d);
        d = fmaf(xv.z, e.z, d);
        d = fmaf(xv.w, e.w, d);
        if (d > best) { best = d; bidx = i; }   // strict > : first-max like jnp.argmax
    }

    const float4 e = semb[bidx];
    float s = fabsf(xv.x - e.x) + fabsf(xv.y - e.y)
            + fabsf(xv.z - e.z) + fabsf(xv.w - e.w);

    // warp reduce
    #pragma unroll
    for (int off = 16; off > 0; off >>= 1)
        s += __shfl_xor_sync(0xFFFFFFFFu, s, off);

    __shared__ float red[THREADS / 32];
    const int wid = threadIdx.x >> 5;
    const int lid = threadIdx.x & 31;
    if (lid == 0) red[wid] = s;
    __syncthreads();

    if (wid == 0) {
        float v = (lid < THREADS / 32) ? red[lid] : 0.0f;
        #pragma unroll
        for (int off = 4; off > 0; off >>= 1)
            v += __shfl_xor_sync(0xFFFFFFFFu, v, off);
        if (lid == 0) g_blocksums[blockIdx.x] = v;
    }
}

__global__ void vq_finish_kernel(float* __restrict__ out)
{
    // one block of 128 threads reduces GRID partial sums
    float v = g_blocksums[threadIdx.x];
    #pragma unroll
    for (int off = 16; off > 0; off >>= 1)
        v += __shfl_xor_sync(0xFFFFFFFFu, v, off);

    __shared__ float red[4];
    const int wid = threadIdx.x >> 5;
    const int lid = threadIdx.x & 31;
    if (lid == 0) red[wid] = v;
    __syncthreads();
    if (threadIdx.x == 0) {
        float t = red[0] + red[1] + red[2] + red[3];
        // loss = mean|x - e| + mean|e - x| = 2 * sum / (B*L*DIM)
        out[0] = 2.0f * t / NELEM;
    }
}

extern "C" void kernel_launch(void* const* d_in, const int* in_sizes, int n_in,
                              void* d_out, int out_size)
{
    const float4* x   = (const float4*)d_in[0];   // [8,4096,4] f32
    const float4* emb = (const float4*)d_in[1];   // [8192,4]  f32
    float* out = (float*)d_out;

    const int smem = NUM_EMB * sizeof(float4);    // 128 KB dynamic
    cudaFuncSetAttribute(vq_main_kernel,
                         cudaFuncAttributeMaxDynamicSharedMemorySize, smem);

    vq_main_kernel<<<GRID, THREADS, smem>>>(x, emb);
    vq_finish_kernel<<<1, GRID>>>(out);
}

// round 2
// speedup vs baseline: 1.5986x; 1.5986x over previous
#include <cuda_runtime.h>
#include <cuda_bf16.h>
#include <float.h>

#define NUM_EMB   8192
#define NTOK      32768           // B*L = 8*4096
#define NELEM     131072.0f       // B*L*DIM
#define TPB       224             // 7 warps
#define GRID      147             // 147*224 = 32928 >= 32768, one wave on 148 SMs

typedef unsigned long long u64;

__device__ float g_blocksums[GRID];

// ---- packed f32x2 helpers (sm_103a) ----
__device__ __forceinline__ u64 pack2(float lo, float hi) {
    u64 r; asm("mov.b64 %0, {%1, %2};" : "=l"(r) : "f"(lo), "f"(hi)); return r;
}
__device__ __forceinline__ void unpack2(u64 v, float& lo, float& hi) {
    asm("mov.b64 {%0, %1}, %2;" : "=f"(lo), "=f"(hi) : "l"(v));
}
__device__ __forceinline__ u64 mul2(u64 a, u64 b) {
    u64 r; asm("mul.rn.f32x2 %0, %1, %2;" : "=l"(r) : "l"(a), "l"(b)); return r;
}
__device__ __forceinline__ u64 fma2(u64 a, u64 b, u64 c) {
    u64 r; asm("fma.rn.f32x2 %0, %1, %2, %3;" : "=l"(r) : "l"(a), "l"(b), "l"(c)); return r;
}

__global__ __launch_bounds__(TPB, 1)
void vq_main_kernel(const float4* __restrict__ x,
                    const float4* __restrict__ emb)
{
    extern __shared__ float smem[];
    float* sX = smem;                 // [8192] x-components
    float* sY = smem + NUM_EMB;       // [8192]
    float* sZ = smem + 2 * NUM_EMB;
    float* sW = smem + 3 * NUM_EMB;   // total 128 KB

    // SoA transpose of the codebook into shared memory
    for (int i = threadIdx.x; i < NUM_EMB; i += TPB) {
        const float4 e = emb[i];
        sX[i] = e.x; sY[i] = e.y; sZ[i] = e.z; sW[i] = e.w;
    }
    __syncthreads();

    const int tok = blockIdx.x * TPB + threadIdx.x;
    const bool active = (tok < NTOK);

    float s = 0.0f;
    if (active) {
        const float4 xv = x[tok];
        // broadcast x components into both f32x2 lanes
        const u64 xx = pack2(xv.x, xv.x);
        const u64 xy = pack2(xv.y, xv.y);
        const u64 xz = pack2(xv.z, xv.z);
        const u64 xw = pack2(xv.w, xv.w);

        // view SoA arrays as pairs-of-f32x2 (4 embeddings per longlong2)
        const longlong2* sX2 = (const longlong2*)sX;
        const longlong2* sY2 = (const longlong2*)sY;
        const longlong2* sZ2 = (const longlong2*)sZ;
        const longlong2* sW2 = (const longlong2*)sW;

        float best = -FLT_MAX;
        int   gbase = 0;

        #pragma unroll 4
        for (int g = 0; g < NUM_EMB / 8; ++g) {
            const int k0 = 2 * g, k1 = 2 * g + 1;
            const longlong2 X0 = sX2[k0], Y0 = sY2[k0], Z0 = sZ2[k0], W0 = sW2[k0];
            const longlong2 X1 = sX2[k1], Y1 = sY2[k1], Z1 = sZ2[k1], W1 = sW2[k1];

            // dots for embeddings 8g+0..8g+7, two per packed op
            u64 a = mul2(xx, (u64)X0.x); a = fma2(xy, (u64)Y0.x, a);
            a = fma2(xz, (u64)Z0.x, a);  a = fma2(xw, (u64)W0.x, a);
            u64 b = mul2(xx, (u64)X0.y); b = fma2(xy, (u64)Y0.y, b);
            b = fma2(xz, (u64)Z0.y, b);  b = fma2(xw, (u64)W0.y, b);
            u64 c = mul2(xx, (u64)X1.x); c = fma2(xy, (u64)Y1.x, c);
            c = fma2(xz, (u64)Z1.x, c);  c = fma2(xw, (u64)W1.x, c);
            u64 d = mul2(xx, (u64)X1.y); d = fma2(xy, (u64)Y1.y, d);
            d = fma2(xz, (u64)Z1.y, d);  d = fma2(xw, (u64)W1.y, d);

            float d0, d1, d2, d3, d4, d5, d6, d7;
            unpack2(a, d0, d1); unpack2(b, d2, d3);
            unpack2(c, d4, d5); unpack2(d, d6, d7);

            // FMNMX tree on the alu pipe (overlaps the fma pipe)
            const float m = fmaxf(fmaxf(fmaxf(d0, d1), fmaxf(d2, d3)),
                                  fmaxf(fmaxf(d4, d5), fmaxf(d6, d7)));
            if (m > best) { best = m; gbase = g << 3; }  // strict >: first group wins
        }

        // re-scan winning group of 8: first max inside it == global first argmax
        float bex = 0.f, bey = 0.f, bez = 0.f, bew = 0.f;
        float lb = -FLT_MAX;
        #pragma unroll
        for (int j = 0; j < 8; ++j) {
            const int i = gbase + j;
            const float ex = sX[i], ey = sY[i], ez = sZ[i], ew = sW[i];
            const float dj = fmaf(xv.w, ew, fmaf(xv.z, ez, fmaf(xv.y, ey, xv.x * ex)));
            if (dj > lb) { lb = dj; bex = ex; bey = ey; bez = ez; bew = ew; }
        }

        s = fabsf(xv.x - bex) + fabsf(xv.y - bey)
          + fabsf(xv.z - bez) + fabsf(xv.w - bew);
    }

    // block reduction of the |x-e| partial sums
    #pragma unroll
    for (int off = 16; off > 0; off >>= 1)
        s += __shfl_xor_sync(0xFFFFFFFFu, s, off);

    __shared__ float red[TPB / 32];
    const int wid = threadIdx.x >> 5;
    const int lid = threadIdx.x & 31;
    if (lid == 0) red[wid] = s;
    __syncthreads();

    if (threadIdx.x == 0) {
        float v = 0.0f;
        #pragma unroll
        for (int w = 0; w < TPB / 32; ++w) v += red[w];
        g_blocksums[blockIdx.x] = v;
    }
}

__global__ void vq_finish_kernel(float* __restrict__ out)
{
    // single warp reduces GRID partial sums
    float v = 0.0f;
    for (int i = threadIdx.x; i < GRID; i += 32) v += g_blocksums[i];
    #pragma unroll
    for (int off = 16; off > 0; off >>= 1)
        v += __shfl_xor_sync(0xFFFFFFFFu, v, off);
    if (threadIdx.x == 0)
        out[0] = 2.0f * v / NELEM;   // mean|x-e| + mean|e-x| = 2*sum/NELEM
}

extern "C" void kernel_launch(void* const* d_in, const int* in_sizes, int n_in,
                              void* d_out, int out_size)
{
    const float4* x   = (const float4*)d_in[0];   // [8,4096,4] f32
    const float4* emb = (const float4*)d_in[1];   // [8192,4]  f32
    float* out = (float*)d_out;

    const int smem = 4 * NUM_EMB * sizeof(float); // 128 KB dynamic
    cudaFuncSetAttribute(vq_main_kernel,
                         cudaFuncAttributeMaxDynamicSharedMemorySize, smem);

    vq_main_kernel<<<GRID, TPB, smem>>>(x, emb);
    vq_finish_kernel<<<1, 32>>>(out);
}

// round 3
// speedup vs baseline: 1.6156x; 1.0106x over previous
#include <cuda_runtime.h>
#include <cuda_bf16.h>
#include <float.h>

#define NUM_EMB   8192
#define HALF_EMB  4096
#define NTOK      32768           // B*L
#define NELEM     131072.0f      // B*L*DIM
#define TPB       224             // 7 warps
#define NCHUNK    147             // 147*224 = 32928 >= 32768 tokens
#define GRID1     (2 * NCHUNK)    // two codebook halves
#define TPB2      256
#define GRID2     (NTOK / TPB2)   // 128

typedef unsigned long long u64;

// scratch (no device allocation allowed): per-token candidate per half + block sums
__device__ float2 g_best[2][NTOK];       // .x = best dot, .y = __int_as_float(global idx)
__device__ float  g_blocksums[GRID2];

// ---- packed f32x2 helpers (sm_103a) ----
__device__ __forceinline__ u64 pack2(float lo, float hi) {
    u64 r; asm("mov.b64 %0, {%1, %2};" : "=l"(r) : "f"(lo), "f"(hi)); return r;
}
__device__ __forceinline__ void unpack2(u64 v, float& lo, float& hi) {
    asm("mov.b64 {%0, %1}, %2;" : "=f"(lo), "=f"(hi) : "l"(v));
}
__device__ __forceinline__ u64 mul2(u64 a, u64 b) {
    u64 r; asm("mul.rn.f32x2 %0, %1, %2;" : "=l"(r) : "l"(a), "l"(b)); return r;
}
__device__ __forceinline__ u64 fma2(u64 a, u64 b, u64 c) {
    u64 r; asm("fma.rn.f32x2 %0, %1, %2, %3;" : "=l"(r) : "l"(a), "l"(b), "l"(c)); return r;
}

// Phase 1: each CTA scans one half of the codebook for 224 tokens.
__global__ __launch_bounds__(TPB, 2)
void vq_scan_kernel(const float4* __restrict__ x,
                    const float4* __restrict__ emb)
{
    extern __shared__ float smem[];
    float* sX = smem;                   // [4096]
    float* sY = smem + HALF_EMB;
    float* sZ = smem + 2 * HALF_EMB;
    float* sW = smem + 3 * HALF_EMB;    // 64 KB total

    const int half  = blockIdx.x & 1;           // 0 or 1
    const int chunk = blockIdx.x >> 1;          // 0..146
    const int ebase = half * HALF_EMB;

    // SoA transpose of this half of the codebook
    for (int i = threadIdx.x; i < HALF_EMB; i += TPB) {
        const float4 e = emb[ebase + i];
        sX[i] = e.x; sY[i] = e.y; sZ[i] = e.z; sW[i] = e.w;
    }
    __syncthreads();

    const int tok = chunk * TPB + threadIdx.x;
    if (tok >= NTOK) return;

    const float4 xv = x[tok];
    const u64 xx = pack2(xv.x, xv.x);
    const u64 xy = pack2(xv.y, xv.y);
    const u64 xz = pack2(xv.z, xv.z);
    const u64 xw = pack2(xv.w, xv.w);

    const longlong2* sX2 = (const longlong2*)sX;
    const longlong2* sY2 = (const longlong2*)sY;
    const longlong2* sZ2 = (const longlong2*)sZ;
    const longlong2* sW2 = (const longlong2*)sW;

    float best = -FLT_MAX;
    int   gbase = 0;

    #pragma unroll 4
    for (int g = 0; g < HALF_EMB / 8; ++g) {
        const int k0 = 2 * g, k1 = 2 * g + 1;
        const longlong2 X0 = sX2[k0], Y0 = sY2[k0], Z0 = sZ2[k0], W0 = sW2[k0];
        const longlong2 X1 = sX2[k1], Y1 = sY2[k1], Z1 = sZ2[k1], W1 = sW2[k1];

        u64 a = mul2(xx, (u64)X0.x); a = fma2(xy, (u64)Y0.x, a);
        a = fma2(xz, (u64)Z0.x, a);  a = fma2(xw, (u64)W0.x, a);
        u64 b = mul2(xx, (u64)X0.y); b = fma2(xy, (u64)Y0.y, b);
        b = fma2(xz, (u64)Z0.y, b);  b = fma2(xw, (u64)W0.y, b);
        u64 c = mul2(xx, (u64)X1.x); c = fma2(xy, (u64)Y1.x, c);
        c = fma2(xz, (u64)Z1.x, c);  c = fma2(xw, (u64)W1.x, c);
        u64 d = mul2(xx, (u64)X1.y); d = fma2(xy, (u64)Y1.y, d);
        d = fma2(xz, (u64)Z1.y, d);  d = fma2(xw, (u64)W1.y, d);

        float d0, d1, d2, d3, d4, d5, d6, d7;
        unpack2(a, d0, d1); unpack2(b, d2, d3);
        unpack2(c, d4, d5); unpack2(d, d6, d7);

        const float m = fmaxf(fmaxf(fmaxf(d0, d1), fmaxf(d2, d3)),
                              fmaxf(fmaxf(d4, d5), fmaxf(d6, d7)));
        if (m > best) { best = m; gbase = g << 3; }  // strict >: first group wins
    }

    // re-scan the winning group of 8 -> first max in that group
    float lb = -FLT_MAX;
    int   bj = 0;
    #pragma unroll
    for (int j = 0; j < 8; ++j) {
        const int i = gbase + j;
        const float dj = fmaf(xv.w, sW[i],
                         fmaf(xv.z, sZ[i],
                         fmaf(xv.y, sY[i], xv.x * sX[i])));
        if (dj > lb) { lb = dj; bj = i; }
    }

    g_best[half][tok] = make_float2(lb, __int_as_float(ebase + bj));
}

// Phase 2: combine halves, gather winning embedding, accumulate |x - e|.
__global__ __launch_bounds__(TPB2)
void vq_combine_kernel(const float4* __restrict__ x,
                       const float4* __restrict__ emb)
{
    const int tok = blockIdx.x * TPB2 + threadIdx.x;

    const float2 b0 = g_best[0][tok];
    const float2 b1 = g_best[1][tok];
    // strict >: half 0 wins ties -> global first-max semantics
    const int idx = (b1.x > b0.x) ? __float_as_int(b1.y) : __float_as_int(b0.y);

    const float4 e  = emb[idx];      // L2-resident gather
    const float4 xv = x[tok];
    float s = fabsf(xv.x - e.x) + fabsf(xv.y - e.y)
            + fabsf(xv.z - e.z) + fabsf(xv.w - e.w);

    #pragma unroll
    for (int off = 16; off > 0; off >>= 1)
        s += __shfl_xor_sync(0xFFFFFFFFu, s, off);

    __shared__ float red[TPB2 / 32];
    const int wid = threadIdx.x >> 5;
    const int lid = threadIdx.x & 31;
    if (lid == 0) red[wid] = s;
    __syncthreads();

    if (threadIdx.x == 0) {
        float v = 0.0f;
        #pragma unroll
        for (int w = 0; w < TPB2 / 32; ++w) v += red[w];
        g_blocksums[blockIdx.x] = v;
    }
}

__global__ void vq_finish_kernel(float* __restrict__ out)
{
    float v = 0.0f;
    for (int i = threadIdx.x; i < GRID2; i += 32) v += g_blocksums[i];
    #pragma unroll
    for (int off = 16; off > 0; off >>= 1)
        v += __shfl_xor_sync(0xFFFFFFFFu, v, off);
    if (threadIdx.x == 0)
        out[0] = 2.0f * v / NELEM;   // mean|x-e| + mean|e-x| = 2*sum/NELEM
}

extern "C" void kernel_launch(void* const* d_in, const int* in_sizes, int n_in,
                              void* d_out, int out_size)
{
    const float4* x   = (const float4*)d_in[0];   // [8,4096,4] f32
    const float4* emb = (const float4*)d_in[1];   // [8192,4]  f32
    float* out = (float*)d_out;

    const int smem = 4 * HALF_EMB * sizeof(float);  // 64 KB dynamic
    cudaFuncSetAttribute(vq_scan_kernel,
                         cudaFuncAttributeMaxDynamicSharedMemorySize, smem);

    vq_scan_kernel<<<GRID1, TPB, smem>>>(x, emb);
    vq_combine_kernel<<<GRID2, TPB2>>>(x, emb);
    vq_finish_kernel<<<1, 32>>>(out);
}